// round 6
// baseline (speedup 1.0000x reference)
#include <cuda_runtime.h>

// ---------------------------------------------------------------------------
// RandomProjectionQuantizer — single fused kernel, vanilla CUDA.
//   h[t,:]  = hidden[t, 0:320] @ P[320, 16]     (L2-normalize SKIPPED:
//                                                argmax is invariant to a
//                                                positive per-row scale)
//   out[t]  = argmax_k <h[t], CB[k]>            first-index tie-break
//
// Output written as FLOAT32 label values (int32 and int64 both failed the
// harness comparison; labels <= 8191 are exact in fp32).
//
// Inputs bound BY ELEMENT COUNT (robust to harness ordering):
//   hidden = 5,120,000 elems (largest), P = 5,120 (smallest), CB = 131,072.
// ---------------------------------------------------------------------------

#define IN_DIM  320
#define E       16
#define CHUNK   512            // codes staged in smem per iteration (32 KB)
#define TOKC    64             // tokens per CTA
#define THREADS 256
#define SLICES  4              // threads cooperating per token in argmax
#define KPT     (CHUNK / SLICES)   // 128 codes per thread per chunk

union SmemU {
    float              Pt[E * IN_DIM];     // 20 KB, projection phase only
    float              cb[CHUNK * E];      // 32 KB, argmax phase only
    unsigned long long keys[THREADS];      //  2 KB, final reduce only
};

__global__ __launch_bounds__(THREADS)
void rpq_fused(const float* __restrict__ hs,
               const float* __restrict__ P,
               const float* __restrict__ CB,
               float* __restrict__ out,
               int ntok, int kcodes)
{
    __shared__ SmemU u;
    __shared__ float h_s[TOKC][E];         // 4 KB, lives across both phases

    const int tid  = threadIdx.x;
    const int base = blockIdx.x * TOKC;

    // ---- phase 1a: stage P transposed ([e][d] -> conflict-free LDS) -------
    for (int i = tid; i < IN_DIM * E; i += THREADS) {
        int d = i >> 4, e = i & 15;        // P is [d][e] row-major
        u.Pt[e * IN_DIM + d] = P[i];
    }
    __syncthreads();

    // ---- phase 1b: projection, one warp per token --------------------------
    const int warp = tid >> 5, lane = tid & 31;
    for (int pass = 0; pass < TOKC / 8; ++pass) {
        int tl = pass * 8 + warp;
        int tg = base + tl;
        float acc[E];
#pragma unroll
        for (int e = 0; e < E; e++) acc[e] = 0.f;
        if (tg < ntok) {
            const float* row = hs + (long long)tg * IN_DIM;
#pragma unroll
            for (int j = 0; j < IN_DIM / 32; j++) {
                int d = lane + 32 * j;
                float x = row[d];          // coalesced
#pragma unroll
                for (int e = 0; e < E; e++)
                    acc[e] = fmaf(x, u.Pt[e * IN_DIM + d], acc[e]);
            }
        }
#pragma unroll
        for (int e = 0; e < E; e++) {
#pragma unroll
            for (int o = 16; o > 0; o >>= 1)
                acc[e] += __shfl_xor_sync(0xffffffffu, acc[e], o);
        }
        if (lane < E) h_s[tl][lane] = acc[lane];
    }
    __syncthreads();                       // Pt reads done; h_s complete

    // ---- phase 2: fused score + argmax ------------------------------------
    const int tl    = tid & (TOKC - 1);    // token owned by this thread
    const int slice = tid >> 6;            // which quarter of each chunk

    float hreg[E];
#pragma unroll
    for (int e = 0; e < E; e++) hreg[e] = h_s[tl][e];

    float best = -3.402823466e38f;
    int   bidx = 0;

    const int nchunks = kcodes / CHUNK;
    for (int c = 0; c < nchunks; ++c) {
        {
            const float4* src = (const float4*)(CB + (long long)c * CHUNK * E);
            float4* dst = (float4*)u.cb;
            for (int i = tid; i < CHUNK * E / 4; i += THREADS)
                dst[i] = src[i];
        }
        __syncthreads();

        const int k0 = slice * KPT;
        for (int k = 0; k < KPT; ++k) {
            const float* cbr = &u.cb[(k0 + k) * E];   // warp-broadcast reads
            float s = 0.f;
#pragma unroll
            for (int e = 0; e < E; e++) s = fmaf(hreg[e], cbr[e], s);
            if (s > best) { best = s; bidx = c * CHUNK + k0 + k; }  // keep first
        }
        __syncthreads();                   // chunk consumed; safe to overwrite
    }

    // ---- phase 3: combine the SLICES candidates per token ------------------
    // Sortable key: (monotone fp32 bits) << 32 | (0x7FFFFFFF - idx)
    // -> max picks highest score, then smallest index (jnp.argmax semantics).
    unsigned ub = __float_as_uint(best);
    ub = (ub & 0x80000000u) ? ~ub : (ub | 0x80000000u);
    unsigned long long key =
        ((unsigned long long)ub << 32) | (unsigned)(0x7FFFFFFF - bidx);

    u.keys[tid] = key;
    __syncthreads();

    if (slice == 0) {
        unsigned long long k0 = u.keys[tl];
        unsigned long long k1 = u.keys[tl + 64];
        unsigned long long k2 = u.keys[tl + 128];
        unsigned long long k3 = u.keys[tl + 192];
        if (k1 > k0) k0 = k1;
        if (k2 > k0) k0 = k2;
        if (k3 > k0) k0 = k3;
        int tg = base + tl;
        if (tg < ntok)
            out[tg] = (float)(0x7FFFFFFF - (int)(k0 & 0xFFFFFFFFull));
    }
}

// Zero-fill any tail of the output buffer beyond the label region, so no
// 0xAA poison survives in elements we don't own.
__global__ void rpq_tail(float* __restrict__ out, int ntok, int total) {
    int i = ntok + blockIdx.x * blockDim.x + threadIdx.x;
    if (i < total) out[i] = 0.f;
}

// ---------------------------------------------------------------------------
extern "C" void kernel_launch(void* const* d_in, const int* in_sizes, int n_in,
                              void* d_out, int out_size) {
    // Bind by element count: hidden (largest), P (smallest), CB (remaining).
    int ih = 0, ip = 0;
    for (int i = 1; i < n_in; i++) {
        if (in_sizes[i] > in_sizes[ih]) ih = i;
        if (in_sizes[i] < in_sizes[ip]) ip = i;
    }
    int ic = 0;
    for (int i = 0; i < n_in; i++)
        if (i != ih && i != ip) ic = i;

    const float* hs = (const float*)d_in[ih];
    const float* P  = (const float*)d_in[ip];
    const float* CB = (const float*)d_in[ic];
    float* out = (float*)d_out;            // labels stored as float32

    int ntok   = in_sizes[ih] / IN_DIM;    // 16000
    int kcodes = in_sizes[ic] / E;         // 8192

    int grid = (ntok + TOKC - 1) / TOKC;   // 250 CTAs
    rpq_fused<<<grid, THREADS>>>(hs, P, CB, out, ntok, kcodes);

    if (out_size > ntok) {
        int tail = out_size - ntok;
        rpq_tail<<<(tail + 255) / 256, 256>>>(out, ntok, out_size);
    }
}

// round 7
// speedup vs baseline: 1.3747x; 1.3747x over previous
#include <cuda_runtime.h>

// ---------------------------------------------------------------------------
// RandomProjectionQuantizer
//   h[t,:] = hidden[t,0:320] @ P[320,16]   (L2-normalize skipped: argmax is
//                                           invariant to positive row scale)
//   out[t] = (float)argmax_k <h[t], CB[k]> first-index ties; float32 output
//                                           (proven contract in R6)
//
// Argmax kernel: codes packed in PAIRS into f32x2 lanes (cb_pair[e] =
// (cb[2p][e], cb[2p+1][e])), h duplicated into both halves. One fma2 = one
// dim for two codes; the packed accumulator ends as (score_2p, score_2p+1)
// with no horizontal reduce. Cross-chunk combine: atomicMax on sortable
// (score_bits, 0x7FFFFFFF - idx) keys.
// ---------------------------------------------------------------------------

#define IN_DIM   320
#define E        16
#define CHUNK    512                 // codes per CTA (y-dim of grid)
#define NPAIR    (CHUNK / 2)         // 256 code pairs, 32 KB packed smem
#define THREADS  128
#define TPT      2                   // tokens per thread
#define TOKB     (THREADS * TPT)     // 256 tokens per CTA
#define TOKENS_MAX 16000

__device__ __align__(16) float              g_h[TOKENS_MAX * E];
__device__ __align__(16) unsigned long long g_keys[TOKENS_MAX];

typedef unsigned long long u64;

// ---- packed f32x2 ops (sm_100a+) ------------------------------------------
static __device__ __forceinline__ u64 mul2(u64 a, u64 b) {
    u64 d; asm("mul.rn.f32x2 %0, %1, %2;" : "=l"(d) : "l"(a), "l"(b)); return d;
}
static __device__ __forceinline__ u64 fma2(u64 a, u64 b, u64 c) {
    u64 d; asm("fma.rn.f32x2 %0, %1, %2, %3;" : "=l"(d) : "l"(a), "l"(b), "l"(c)); return d;
}
static __device__ __forceinline__ u64 add2(u64 a, u64 b) {
    u64 d; asm("add.rn.f32x2 %0, %1, %2;" : "=l"(d) : "l"(a), "l"(b)); return d;
}
static __device__ __forceinline__ u64 pack2(float lo, float hi) {
    u64 d; asm("mov.b64 %0, {%1, %2};" : "=l"(d) : "f"(lo), "f"(hi)); return d;
}
static __device__ __forceinline__ void unpack2(float& lo, float& hi, u64 v) {
    asm("mov.b64 {%0, %1}, %2;" : "=f"(lo), "=f"(hi) : "l"(v));
}

// ---------------------------------------------------------------------------
__global__ void rpq_init_keys(int ntok) {
    int t = blockIdx.x * blockDim.x + threadIdx.x;
    if (t < ntok) g_keys[t] = 0ull;
}

// ---------------------------------------------------------------------------
// Projection: one warp per token, P transposed in smem.
__global__ void rpq_proj(const float* __restrict__ hs,
                         const float* __restrict__ P, int ntok) {
    __shared__ float Pt[E * IN_DIM];
    int tid = threadIdx.x;
    for (int i = tid; i < IN_DIM * E; i += blockDim.x) {
        int d = i >> 4, e = i & 15;
        Pt[e * IN_DIM + d] = P[i];
    }
    __syncthreads();

    int warp = tid >> 5, lane = tid & 31;
    int t = blockIdx.x * 4 + warp;
    if (t >= ntok) return;

    const float* row = hs + (long long)t * IN_DIM;
    float acc[E];
#pragma unroll
    for (int e = 0; e < E; e++) acc[e] = 0.f;
#pragma unroll
    for (int j = 0; j < IN_DIM / 32; j++) {
        int d = lane + 32 * j;
        float x = row[d];
#pragma unroll
        for (int e = 0; e < E; e++)
            acc[e] = fmaf(x, Pt[e * IN_DIM + d], acc[e]);
    }
#pragma unroll
    for (int e = 0; e < E; e++) {
#pragma unroll
        for (int o = 16; o > 0; o >>= 1)
            acc[e] += __shfl_xor_sync(0xffffffffu, acc[e], o);
    }
    if (lane < E) g_h[t * E + lane] = acc[lane];
}

// ---------------------------------------------------------------------------
__global__ __launch_bounds__(THREADS)
void rpq_argmax(const float* __restrict__ CB, int ntok, int kcodes) {
    // code-pair packed chunk: cbp[p*16+e] = (CB[2p][e], CB[2p+1][e])
    __shared__ __align__(16) u64 cbp[NPAIR * E];     // 32 KB

    const int tid   = threadIdx.x;
    const int kbase = blockIdx.y * CHUNK;

    // ---- stage + pack: thread i -> pair p = i>>2, elem-quad q = i&3 -------
    for (int i = tid; i < NPAIR * 4; i += THREADS) {
        int p = i >> 2, q = i & 3;
        const float4* c0 = (const float4*)(CB + (long long)(kbase + 2 * p) * E) + q;
        const float4* c1 = (const float4*)(CB + (long long)(kbase + 2 * p + 1) * E) + q;
        float4 a = *c0, b = *c1;
        u64* dst = &cbp[p * E + q * 4];
        dst[0] = pack2(a.x, b.x);
        dst[1] = pack2(a.y, b.y);
        dst[2] = pack2(a.z, b.z);
        dst[3] = pack2(a.w, b.w);
    }

    // ---- load TPT tokens' h, duplicated into both f32x2 halves ------------
    u64  hd[TPT][E];
    int  tok[TPT];
    bool valid[TPT];
#pragma unroll
    for (int i = 0; i < TPT; i++) {
        int t = blockIdx.x * TOKB + tid + i * THREADS;
        tok[i] = t;
        valid[i] = (t < ntok);
        const float4* hv = (const float4*)(g_h + (long long)(valid[i] ? t : 0) * E);
        float4 h0 = hv[0], h1 = hv[1], h2 = hv[2], h3 = hv[3];
        hd[i][0]  = pack2(h0.x, h0.x); hd[i][1]  = pack2(h0.y, h0.y);
        hd[i][2]  = pack2(h0.z, h0.z); hd[i][3]  = pack2(h0.w, h0.w);
        hd[i][4]  = pack2(h1.x, h1.x); hd[i][5]  = pack2(h1.y, h1.y);
        hd[i][6]  = pack2(h1.z, h1.z); hd[i][7]  = pack2(h1.w, h1.w);
        hd[i][8]  = pack2(h2.x, h2.x); hd[i][9]  = pack2(h2.y, h2.y);
        hd[i][10] = pack2(h2.z, h2.z); hd[i][11] = pack2(h2.w, h2.w);
        hd[i][12] = pack2(h3.x, h3.x); hd[i][13] = pack2(h3.y, h3.y);
        hd[i][14] = pack2(h3.z, h3.z); hd[i][15] = pack2(h3.w, h3.w);
    }
    __syncthreads();

    float best[TPT];
    int   bidx[TPT];
#pragma unroll
    for (int i = 0; i < TPT; i++) { best[i] = -3.402823466e38f; bidx[i] = 0; }

    const ulonglong2* pv = (const ulonglong2*)cbp;
    for (int p = 0; p < NPAIR; ++p) {
        // 16 packed elems = 8 x LDS.128, warp-broadcast (same addr all lanes)
        ulonglong2 v0 = pv[p * 8 + 0], v1 = pv[p * 8 + 1];
        ulonglong2 v2 = pv[p * 8 + 2], v3 = pv[p * 8 + 3];
        ulonglong2 v4 = pv[p * 8 + 4], v5 = pv[p * 8 + 5];
        ulonglong2 v6 = pv[p * 8 + 6], v7 = pv[p * 8 + 7];
#pragma unroll
        for (int i = 0; i < TPT; i++) {
            u64 a0 = mul2(hd[i][0],  v0.x);
            u64 a1 = mul2(hd[i][1],  v0.y);
            a0 = fma2(hd[i][2],  v1.x, a0);
            a1 = fma2(hd[i][3],  v1.y, a1);
            a0 = fma2(hd[i][4],  v2.x, a0);
            a1 = fma2(hd[i][5],  v2.y, a1);
            a0 = fma2(hd[i][6],  v3.x, a0);
            a1 = fma2(hd[i][7],  v3.y, a1);
            a0 = fma2(hd[i][8],  v4.x, a0);
            a1 = fma2(hd[i][9],  v4.y, a1);
            a0 = fma2(hd[i][10], v5.x, a0);
            a1 = fma2(hd[i][11], v5.y, a1);
            a0 = fma2(hd[i][12], v6.x, a0);
            a1 = fma2(hd[i][13], v6.y, a1);
            a0 = fma2(hd[i][14], v7.x, a0);
            a1 = fma2(hd[i][15], v7.y, a1);
            a0 = add2(a0, a1);               // (score_2p, score_2p+1)
            float slo, shi;
            unpack2(slo, shi, a0);
            if (slo > best[i]) { best[i] = slo; bidx[i] = 2 * p; }
            if (shi > best[i]) { best[i] = shi; bidx[i] = 2 * p + 1; }
        }
    }

#pragma unroll
    for (int i = 0; i < TPT; i++) {
        if (!valid[i]) continue;
        int gidx = kbase + bidx[i];
        unsigned ub = __float_as_uint(best[i]);
        ub = (ub & 0x80000000u) ? ~ub : (ub | 0x80000000u);  // sortable fp32
        u64 key = ((u64)ub << 32) | (unsigned)(0x7FFFFFFF - gidx);
        atomicMax(&g_keys[tok[i]], key);
    }
}

// ---------------------------------------------------------------------------
__global__ void rpq_finalize(float* __restrict__ out, int ntok, int total) {
    int t = blockIdx.x * blockDim.x + threadIdx.x;
    if (t < ntok)
        out[t] = (float)(0x7FFFFFFF - (int)(g_keys[t] & 0xFFFFFFFFull));
    else if (t < total)
        out[t] = 0.f;
}

// ---------------------------------------------------------------------------
extern "C" void kernel_launch(void* const* d_in, const int* in_sizes, int n_in,
                              void* d_out, int out_size) {
    // Bind by element count: hidden (largest), P (smallest), CB (remaining).
    int ih = 0, ip = 0;
    for (int i = 1; i < n_in; i++) {
        if (in_sizes[i] > in_sizes[ih]) ih = i;
        if (in_sizes[i] < in_sizes[ip]) ip = i;
    }
    int ic = 0;
    for (int i = 0; i < n_in; i++)
        if (i != ih && i != ip) ic = i;

    const float* hs = (const float*)d_in[ih];
    const float* P  = (const float*)d_in[ip];
    const float* CB = (const float*)d_in[ic];
    float* out = (float*)d_out;            // float32 labels (R6-proven)

    int ntok   = in_sizes[ih] / IN_DIM;    // 16000
    int kcodes = in_sizes[ic] / E;         // 8192

    rpq_init_keys<<<(ntok + 255) / 256, 256>>>(ntok);
    rpq_proj<<<(ntok + 3) / 4, 128>>>(hs, P, ntok);

    dim3 g2((ntok + TOKB - 1) / TOKB, kcodes / CHUNK);   // (63, 16)
    rpq_argmax<<<g2, THREADS>>>(CB, ntok, kcodes);

    int total = out_size;
    rpq_finalize<<<(total + 255) / 256, 256>>>(out, ntok, total);
}